// round 2
// baseline (speedup 1.0000x reference)
#include <cuda_runtime.h>
#include <cuda_bf16.h>

// Problem shape (fixed by the reference)
#define BB 16
#define TT 4096
#define HH 512
#define SS 64            // T-chunks per batch
#define TC (TT / SS)     // 64 rows per chunk
#define H4 (HH / 4)      // 128 float4 per row

// Scratch: per (b, chunk): 512 global-sum floats + 512 local-sum floats
__device__ float g_partial[BB * SS * 2 * HH];   // 4 MiB
__device__ int   g_counts[BB * SS];

// Pass 1: each CTA handles one (b, t-chunk), 128 threads x float4 cover H=512.
// Streams 64 rows of 2 KiB, fully coalesced. Both accumulation predicates are
// warp-uniform. Unroll x4 for memory-level parallelism.
__global__ __launch_bounds__(128) void pass1_kernel(
    const float4* __restrict__ x,
    const int* __restrict__ lengths,
    const int* __restrict__ mask)      // bool materialized as int32 by harness
{
    const int blk = blockIdx.x;          // 0 .. B*S-1
    const int b   = blk / SS;
    const int s   = blk % SS;
    const int tid = threadIdx.x;         // 0..127

    const int L  = lengths[b];
    const int t0 = s * TC;

    const float4* __restrict__ xp = x + (size_t)b * TT * H4 + (size_t)t0 * H4 + tid;
    const int* __restrict__ mp = mask + (size_t)b * TT + t0;

    float4 ag = make_float4(0.f, 0.f, 0.f, 0.f);
    float4 al = make_float4(0.f, 0.f, 0.f, 0.f);
    int cnt = 0;

    #pragma unroll 4
    for (int t = 0; t < TC; ++t) {
        float4 v = xp[(size_t)t * H4];
        bool g = (t0 + t) < L;           // warp-uniform
        bool m = (mp[t] != 0);           // warp-uniform broadcast
        if (g) { ag.x += v.x; ag.y += v.y; ag.z += v.z; ag.w += v.w; }
        if (m) { al.x += v.x; al.y += v.y; al.z += v.z; al.w += v.w; cnt++; }
    }

    float4* outp = reinterpret_cast<float4*>(g_partial) + (size_t)blk * (2 * HH / 4);
    outp[tid]      = ag;
    outp[H4 + tid] = al;
    if (tid == 0) g_counts[blk] = cnt;
}

// Pass 2: one CTA per batch row; thread h reduces the 64 chunk-partials and
// writes out[b, h] and out[b, H + h]. ~4 MiB total read, negligible.
__global__ __launch_bounds__(HH) void pass2_kernel(
    const int* __restrict__ lengths,
    float* __restrict__ out)
{
    const int b = blockIdx.x;
    const int h = threadIdx.x;           // 0..511

    float sg = 0.f, sl = 0.f;
    #pragma unroll 8
    for (int s = 0; s < SS; ++s) {
        const float* p = g_partial + (size_t)(b * SS + s) * (2 * HH);
        sg += p[h];
        sl += p[HH + h];
    }

    int cnt = 0;
    #pragma unroll 8
    for (int s = 0; s < SS; ++s) cnt += g_counts[b * SS + s];  // broadcast loads

    const int Lraw = lengths[b];
    const float denom_g = (float)(Lraw > 1 ? Lraw : 1);
    const float denom_l = (float)(cnt  > 1 ? cnt  : 1);

    out[(size_t)b * 2 * HH + h]      = sg / denom_g;
    out[(size_t)b * 2 * HH + HH + h] = sl / denom_l;
}

extern "C" void kernel_launch(void* const* d_in, const int* in_sizes, int n_in,
                              void* d_out, int out_size)
{
    const float4* x       = (const float4*)d_in[0];   // [B,T,H] f32
    const int*    lengths = (const int*)d_in[1];      // [B] i32
    const int*    mask    = (const int*)d_in[2];      // [B,T] bool -> i32
    float*        out     = (float*)d_out;            // [B, 2H] f32

    pass1_kernel<<<BB * SS, 128>>>(x, lengths, mask);
    pass2_kernel<<<BB, HH>>>(lengths, out);
}

// round 3
// speedup vs baseline: 1.0850x; 1.0850x over previous
#include <cuda_runtime.h>
#include <cuda_bf16.h>

// Problem shape (fixed by the reference)
#define BB 16
#define TT 4096
#define HH 512
#define SS 64            // T-chunks per batch
#define TC (TT / SS)     // 64 rows per chunk
#define H4 (HH / 4)      // 128 float4 per row

// Accumulators: [B][2*HH] floats (128 KiB) + per-batch mask counts.
// Zero-initialized at module load; finalize_kernel re-zeros after each use
// so every graph replay starts from zeros.
__device__ float g_accum[BB * 2 * HH];
__device__ int   g_cnt[BB];

// Pass 1: each CTA handles one (b, t-chunk); 128 threads x float4 cover H=512.
// Streams 64 rows of 2 KiB coalesced (streaming loads, no L2 reuse), then
// REDG-accumulates its 1 KiB of partial sums into g_accum. Predicates are
// warp-uniform; unroll x8 gives deep MLP to hide the 577-cyc DRAM latency.
__global__ __launch_bounds__(128) void pass1_kernel(
    const float4* __restrict__ x,
    const int* __restrict__ lengths,
    const int* __restrict__ mask)      // jax bool materialized as int32
{
    const int blk = blockIdx.x;          // 0 .. B*S-1
    const int b   = blk / SS;
    const int s   = blk % SS;
    const int tid = threadIdx.x;         // 0..127

    const int L  = lengths[b];
    const int t0 = s * TC;

    const float4* __restrict__ xp = x + (size_t)b * TT * H4 + (size_t)t0 * H4 + tid;
    const int* __restrict__ mp = mask + (size_t)b * TT + t0;

    float4 ag = make_float4(0.f, 0.f, 0.f, 0.f);
    float4 al = make_float4(0.f, 0.f, 0.f, 0.f);
    int cnt = 0;

    #pragma unroll 8
    for (int t = 0; t < TC; ++t) {
        float4 v = __ldcs(&xp[(size_t)t * H4]);
        bool g = (t0 + t) < L;           // warp-uniform
        bool m = (mp[t] != 0);           // warp-uniform broadcast
        if (g) { ag.x += v.x; ag.y += v.y; ag.z += v.z; ag.w += v.w; }
        if (m) { al.x += v.x; al.y += v.y; al.z += v.z; al.w += v.w; cnt++; }
    }

    float* acc = g_accum + (size_t)b * 2 * HH;
    const int h = 4 * tid;
    atomicAdd(&acc[h + 0], ag.x);
    atomicAdd(&acc[h + 1], ag.y);
    atomicAdd(&acc[h + 2], ag.z);
    atomicAdd(&acc[h + 3], ag.w);
    atomicAdd(&acc[HH + h + 0], al.x);
    atomicAdd(&acc[HH + h + 1], al.y);
    atomicAdd(&acc[HH + h + 2], al.z);
    atomicAdd(&acc[HH + h + 3], al.w);
    if (tid == 0 && cnt) atomicAdd(&g_cnt[b], cnt);
}

// Finalize: one CTA per batch; 1024 threads cover out[b, 0:2H].
// Divides by the proper denominator, then resets the accumulators so the
// next (graph-replayed) launch sequence starts from zero.
__global__ __launch_bounds__(1024) void finalize_kernel(
    const int* __restrict__ lengths,
    float* __restrict__ out)
{
    const int b = blockIdx.x;
    const int j = threadIdx.x;           // 0..1023

    const int cnt  = g_cnt[b];           // broadcast
    const int Lraw = lengths[b];
    const float denom = (j < HH) ? (float)(Lraw > 1 ? Lraw : 1)
                                 : (float)(cnt  > 1 ? cnt  : 1);

    const size_t idx = (size_t)b * 2 * HH + j;
    out[idx] = g_accum[idx] / denom;

    __syncthreads();                     // all reads of g_cnt[b] done
    g_accum[idx] = 0.f;
    if (j == 0) g_cnt[b] = 0;
}

extern "C" void kernel_launch(void* const* d_in, const int* in_sizes, int n_in,
                              void* d_out, int out_size)
{
    const float4* x       = (const float4*)d_in[0];   // [B,T,H] f32
    const int*    lengths = (const int*)d_in[1];      // [B] i32
    const int*    mask    = (const int*)d_in[2];      // [B,T] bool -> i32
    float*        out     = (float*)d_out;            // [B, 2H] f32

    pass1_kernel<<<BB * SS, 128>>>(x, lengths, mask);
    finalize_kernel<<<BB, 1024>>>(lengths, out);
}